// round 1
// baseline (speedup 1.0000x reference)
#include <cuda_runtime.h>
#include <math.h>

#define N 8192
#define D 512
#define NT 64                      // 8192 / 128 tiles per dim
#define NPAIRS (NT*(NT+1)/2)       // 2080 upper-triangle tile pairs
#define BM 128
#define BK 16

// Scratch: normalized rows + global accumulator (device globals; no allocs).
__device__ float  g_normed[N * D];
__device__ double g_accum;

// ---------------------------------------------------------------------------
// Kernel 1: row L2-normalize. One block (128 threads) per row; each thread
// owns one float4 (4 floats) of the 512-wide row.
// Also zeroes the accumulator (safe: gram_kernel runs strictly after).
// ---------------------------------------------------------------------------
__global__ __launch_bounds__(128) void normalize_kernel(const float* __restrict__ in) {
    int row = blockIdx.x;
    int t   = threadIdx.x;
    if (row == 0 && t == 0) g_accum = 0.0;

    const float4* src = (const float4*)(in + (size_t)row * D);
    float4 v = src[t];
    float ss = v.x*v.x + v.y*v.y + v.z*v.z + v.w*v.w;

    #pragma unroll
    for (int o = 16; o; o >>= 1) ss += __shfl_xor_sync(0xffffffffu, ss, o);

    __shared__ float ws[4];
    if ((t & 31) == 0) ws[t >> 5] = ss;
    __syncthreads();
    float tot = ws[0] + ws[1] + ws[2] + ws[3];

    // norms ~ sqrt(512) >> eps=1e-8, so plain 1/sqrt matches the reference's
    // max(norm_i*norm_j, eps) denominator exactly in effect.
    float inv = 1.0f / sqrtf(tot);

    float4 o4;
    o4.x = v.x * inv; o4.y = v.y * inv; o4.z = v.z * inv; o4.w = v.w * inv;
    ((float4*)(g_normed + (size_t)row * D))[t] = o4;
}

// ---------------------------------------------------------------------------
// Kernel 2: upper-triangle tiled Gram + relu + reduction.
// Tile pair (bi, bj), bi <= bj. 128x128 C tile, K-chunks of 16, 256 threads,
// 8x8 micro-tile per thread with split-float4 fragments (conflict-free LDS).
// Only pairs with global i < j contribute; final result doubles the sum.
// ---------------------------------------------------------------------------
__global__ __launch_bounds__(256) void gram_kernel() {
    int b = blockIdx.x;
    // decode triangular index: b = bj*(bj+1)/2 + bi, bi in [0, bj]
    int bj = (int)((sqrtf(8.0f * (float)b + 1.0f) - 1.0f) * 0.5f);
    while ((bj + 1) * (bj + 2) / 2 <= b) bj++;
    while (bj * (bj + 1) / 2 > b) bj--;
    int bi = b - bj * (bj + 1) / 2;

    const int rowA = bi * BM;   // i-tile base
    const int rowB = bj * BM;   // j-tile base

    __shared__ float As[BK][132];   // [k][i], padded row (132*4B = 528B, 16B-aligned)
    __shared__ float Bs[BK][132];   // [k][j]

    int t  = threadIdx.x;
    int tx = t & 15;     // 16 j-lanes
    int ty = t >> 4;     // 16 i-lanes

    float c[8][8];
    #pragma unroll
    for (int i = 0; i < 8; i++)
        #pragma unroll
        for (int j = 0; j < 8; j++) c[i][j] = 0.0f;

    for (int k0 = 0; k0 < D; k0 += BK) {
        // Load 128 rows x 16 k-cols for A and B: 512 float4 each, 2 per thread.
        #pragma unroll
        for (int it = 0; it < 2; it++) {
            int idx = t + it * 256;
            int r  = idx >> 2;        // 0..127
            int c4 = idx & 3;         // 0..3  -> k-offset c4*4
            float4 va = *(const float4*)&g_normed[(size_t)(rowA + r) * D + k0 + c4 * 4];
            As[c4*4+0][r] = va.x; As[c4*4+1][r] = va.y;
            As[c4*4+2][r] = va.z; As[c4*4+3][r] = va.w;
            float4 vb = *(const float4*)&g_normed[(size_t)(rowB + r) * D + k0 + c4 * 4];
            Bs[c4*4+0][r] = vb.x; Bs[c4*4+1][r] = vb.y;
            Bs[c4*4+2][r] = vb.z; Bs[c4*4+3][r] = vb.w;
        }
        __syncthreads();

        #pragma unroll
        for (int k = 0; k < BK; k++) {
            float a[8], bb[8];
            // split fragments: [ty*4 .. +3] and [64+ty*4 .. +3] — consecutive
            // float4 across lanes -> conflict-free shared loads
            *(float4*)&a[0]  = *(const float4*)&As[k][ty * 4];
            *(float4*)&a[4]  = *(const float4*)&As[k][64 + ty * 4];
            *(float4*)&bb[0] = *(const float4*)&Bs[k][tx * 4];
            *(float4*)&bb[4] = *(const float4*)&Bs[k][64 + tx * 4];
            #pragma unroll
            for (int i = 0; i < 8; i++)
                #pragma unroll
                for (int j = 0; j < 8; j++)
                    c[i][j] += a[i] * bb[j];
        }
        __syncthreads();
    }

    // Epilogue: relu + strict upper-triangle mask, per-thread sum.
    float local = 0.0f;
    #pragma unroll
    for (int i = 0; i < 8; i++) {
        int li = (i < 4) ? (ty * 4 + i) : (64 + ty * 4 + i - 4);
        int gi = rowA + li;
        #pragma unroll
        for (int j = 0; j < 8; j++) {
            int lj = (j < 4) ? (tx * 4 + j) : (64 + tx * 4 + j - 4);
            int gj = rowB + lj;
            float v = c[i][j];
            if (gi < gj && v > 0.0f) local += v;
        }
    }

    // block reduce
    #pragma unroll
    for (int o = 16; o; o >>= 1) local += __shfl_xor_sync(0xffffffffu, local, o);
    __shared__ float red[8];
    if ((t & 31) == 0) red[t >> 5] = local;
    __syncthreads();
    if (t == 0) {
        float s = 0.0f;
        #pragma unroll
        for (int w = 0; w < 8; w++) s += red[w];
        atomicAdd(&g_accum, (double)s);
    }
}

// ---------------------------------------------------------------------------
// Kernel 3: finalize. mean over full NxN (diagonal contributes exact zeros),
// doubled for symmetry. total_loss == l_id_div (DIV_COEF = 1).
// ---------------------------------------------------------------------------
__global__ void finalize_kernel(float* __restrict__ out, int out_size) {
    double v = 2.0 * g_accum / ((double)N * (double)N);
    float f = (float)v;
    out[0] = f;
    if (out_size > 1) out[1] = f;
}

extern "C" void kernel_launch(void* const* d_in, const int* in_sizes, int n_in,
                              void* d_out, int out_size) {
    const float* id = (const float*)d_in[0];
    normalize_kernel<<<N, 128>>>(id);
    gram_kernel<<<NPAIRS, 256>>>();
    finalize_kernel<<<1, 1>>>((float*)d_out, out_size);
}

// round 3
// speedup vs baseline: 4.1445x; 4.1445x over previous
#include <cuda_runtime.h>
#include <cuda_bf16.h>
#include <cstdint>
#include <math.h>

#define N 8192
#define D 512
#define BM 128
#define NT (N / BM)                 // 64
#define NPAIRS (NT * (NT + 1) / 2)  // 2080
#define BK 64                       // K elements per chunk
#define NCHUNKS (D / BK)            // 8
#define TILE_BYTES (BM * BK * 2)    // 16384 (bf16)
#define SMEM_BYTES (1024 + 4 * TILE_BYTES)

__device__ __nv_bfloat16 g_nrm[N * D];
__device__ double g_accum;

// ---------------------------------------------------------------------------
// PTX helpers (all arch-agnostic: sm_80-era instructions)
// ---------------------------------------------------------------------------
__device__ __forceinline__ uint32_t smem_u32(const void* p) {
    uint32_t a;
    asm("{ .reg .u64 t; cvta.to.shared.u64 t, %1; cvt.u32.u64 %0, t; }" : "=r"(a) : "l"(p));
    return a;
}

__device__ __forceinline__ void cp16(uint32_t saddr, const void* g) {
    asm volatile("cp.async.cg.shared.global [%0], [%1], 16;" :: "r"(saddr), "l"(g) : "memory");
}
__device__ __forceinline__ void cp_commit() {
    asm volatile("cp.async.commit_group;" ::: "memory");
}
template <int NN>
__device__ __forceinline__ void cp_wait() {
    asm volatile("cp.async.wait_group %0;" :: "n"(NN) : "memory");
}

__device__ __forceinline__ void ldsm_x4(uint32_t* r, uint32_t addr) {
    asm volatile("ldmatrix.sync.aligned.m8n8.x4.shared.b16 {%0,%1,%2,%3}, [%4];"
                 : "=r"(r[0]), "=r"(r[1]), "=r"(r[2]), "=r"(r[3]) : "r"(addr));
}

__device__ __forceinline__ void mma16816(float* d, const uint32_t* a, uint32_t b0, uint32_t b1) {
    asm volatile(
        "mma.sync.aligned.m16n8k16.row.col.f32.bf16.bf16.f32 "
        "{%0,%1,%2,%3}, {%4,%5,%6,%7}, {%8,%9}, {%0,%1,%2,%3};"
        : "+f"(d[0]), "+f"(d[1]), "+f"(d[2]), "+f"(d[3])
        : "r"(a[0]), "r"(a[1]), "r"(a[2]), "r"(a[3]), "r"(b0), "r"(b1));
}

// ---------------------------------------------------------------------------
// Kernel 1: row L2-normalize fp32 -> bf16. One 128-thread block per row.
// ---------------------------------------------------------------------------
__global__ __launch_bounds__(128) void normalize_kernel(const float* __restrict__ in) {
    int row = blockIdx.x;
    int t   = threadIdx.x;
    if (row == 0 && t == 0) g_accum = 0.0;

    const float4* src = (const float4*)(in + (size_t)row * D);
    float4 v = src[t];
    float ss = v.x * v.x + v.y * v.y + v.z * v.z + v.w * v.w;

    #pragma unroll
    for (int o = 16; o; o >>= 1) ss += __shfl_xor_sync(0xffffffffu, ss, o);

    __shared__ float ws[4];
    if ((t & 31) == 0) ws[t >> 5] = ss;
    __syncthreads();
    float inv = rsqrtf(ws[0] + ws[1] + ws[2] + ws[3]);

    __nv_bfloat162* dst = (__nv_bfloat162*)(g_nrm + (size_t)row * D);
    dst[2 * t]     = __floats2bfloat162_rn(v.x * inv, v.y * inv);
    dst[2 * t + 1] = __floats2bfloat162_rn(v.z * inv, v.w * inv);
}

// ---------------------------------------------------------------------------
// Kernel 2: upper-triangle 128x128 Gram tiles via mma.sync bf16 (HMMA).
// 256 threads = 8 warps (2 x 4), warp tile 64x32, cp.async double buffer.
// SMEM tiles [128 rows][64 k] bf16, 128B rows, XOR-swizzled 16B chunks.
// ---------------------------------------------------------------------------
extern __shared__ char dynsmem[];

__global__ __launch_bounds__(256) void gram_mma_kernel() {
    int b = blockIdx.x;
    int bj = (int)((sqrtf(8.0f * (float)b + 1.0f) - 1.0f) * 0.5f);
    while ((bj + 1) * (bj + 2) / 2 <= b) bj++;
    while (bj * (bj + 1) / 2 > b) bj--;
    int bi = b - bj * (bj + 1) / 2;

    const __nv_bfloat16* __restrict__ gA = g_nrm + (size_t)bi * BM * D;
    const __nv_bfloat16* __restrict__ gB = g_nrm + (size_t)bj * BM * D;
    const bool diag = (bi == bj);

    int t      = threadIdx.x;
    int wid    = t >> 5;
    int lane   = t & 31;
    int warp_m = wid & 1;    // 2 warps over M (64 each)
    int warp_n = wid >> 1;   // 4 warps over N (32 each)

    uint32_t smem0 = smem_u32(dynsmem);
    uint32_t base  = (smem0 + 1023) & ~1023u;
    uint32_t sA[2] = { base,                  base + TILE_BYTES };
    uint32_t sB[2] = { base + 2 * TILE_BYTES, base + 3 * TILE_BYTES };

    // --- async tile loader: 128 rows x 64 bf16 (= 8 x 16B chunks/row) ---
    auto load_tile = [&](const __nv_bfloat16* __restrict__ g, uint32_t s, int k0) {
        int row = t >> 1;
        const char* gp = (const char*)(g + (size_t)row * D + k0);
        uint32_t srow = s + (uint32_t)row * 128;
        #pragma unroll
        for (int i = 0; i < 4; i++) {
            int c = (t & 1) * 4 + i;
            cp16(srow + (((uint32_t)c ^ (row & 7)) << 4), gp + c * 16);
        }
    };

    float acc[4][4][4];
    #pragma unroll
    for (int mi = 0; mi < 4; mi++)
        #pragma unroll
        for (int nj = 0; nj < 4; nj++)
            #pragma unroll
            for (int r = 0; r < 4; r++) acc[mi][nj][r] = 0.0f;

    // prologue
    load_tile(gA, sA[0], 0);
    load_tile(gB, sB[0], 0);
    cp_commit();

    // precompute ldmatrix lane addressing (row/k parts independent of chunk)
    int a_row = warp_m * 64 + (lane & 15);        // + mi*16
    int a_kq  = (lane >> 4) * 8;                  // + kk*16, element offset
    int b_row = warp_n * 32 + (lane & 7) + (((lane >> 3) & 1) << 3);  // + p*16
    int b_kq  = (lane >> 4) * 8;

    for (int c = 0; c < NCHUNKS; c++) {
        if (c + 1 < NCHUNKS) {
            load_tile(gA, sA[(c + 1) & 1], (c + 1) * BK);
            load_tile(gB, sB[(c + 1) & 1], (c + 1) * BK);
            cp_commit();
            cp_wait<1>();
        } else {
            cp_wait<0>();
        }
        __syncthreads();

        uint32_t a_base = sA[c & 1], b_base = sB[c & 1];
        #pragma unroll
        for (int kk = 0; kk < 4; kk++) {
            uint32_t Af[4][4], Bf[2][4];
            int kchunk = (kk * 16 + a_kq) >> 3;   // 16B-chunk index within row (0..7)
            #pragma unroll
            for (int mi = 0; mi < 4; mi++) {
                int r = a_row + mi * 16;
                ldsm_x4(Af[mi], a_base + (uint32_t)r * 128 +
                                (((uint32_t)kchunk ^ (r & 7)) << 4));
            }
            #pragma unroll
            for (int p = 0; p < 2; p++) {
                int r = b_row + p * 16;
                ldsm_x4(Bf[p], b_base + (uint32_t)r * 128 +
                               (((uint32_t)kchunk ^ (r & 7)) << 4));
            }
            #pragma unroll
            for (int mi = 0; mi < 4; mi++)
                #pragma unroll
                for (int nj = 0; nj < 4; nj++)
                    mma16816(acc[mi][nj], Af[mi],
                             Bf[nj >> 1][nj & 1], Bf[nj >> 1][(nj & 1) + 2]);
        }
        __syncthreads();
    }

    // Epilogue: relu + (strict upper mask on diagonal tiles), per-lane sum.
    // acc[mi][nj]: r0,r1 at row g, col c0/c0+1 ; r2,r3 at row g+8.
    float local = 0.0f;
    int lrow0 = warp_m * 64 + (lane >> 2);
    int lcol0 = warp_n * 32 + (lane & 3) * 2;
    #pragma unroll
    for (int mi = 0; mi < 4; mi++) {
        #pragma unroll
        for (int nj = 0; nj < 4; nj++) {
            int rm = lrow0 + mi * 16;
            int cn = lcol0 + nj * 8;
            #pragma unroll
            for (int r = 0; r < 4; r++) {
                int im = rm + (r >> 1) * 8;
                int jn = cn + (r & 1);
                float v = acc[mi][nj][r];
                bool ok = diag ? (im < jn) : true;
                if (ok && v > 0.0f) local += v;
            }
        }
    }

    #pragma unroll
    for (int o = 16; o; o >>= 1) local += __shfl_xor_sync(0xffffffffu, local, o);
    __shared__ float red[8];
    if (lane == 0) red[wid] = local;
    __syncthreads();
    if (t == 0) {
        float s = 0.0f;
        #pragma unroll
        for (int w = 0; w < 8; w++) s += red[w];
        atomicAdd(&g_accum, (double)s);
    }
}

// ---------------------------------------------------------------------------
// Kernel 3: finalize. Off-diagonal symmetric sum doubled, mean over N*N.
// ---------------------------------------------------------------------------
__global__ void finalize_kernel(float* __restrict__ out, int out_size) {
    double v = 2.0 * g_accum / ((double)N * (double)N);
    float f = (float)v;
    out[0] = f;
    if (out_size > 1) out[1] = f;
}

extern "C" void kernel_launch(void* const* d_in, const int* in_sizes, int n_in,
                              void* d_out, int out_size) {
    const float* id = (const float*)d_in[0];
    cudaFuncSetAttribute(gram_mma_kernel, cudaFuncAttributeMaxDynamicSharedMemorySize,
                         SMEM_BYTES);
    normalize_kernel<<<N, 128>>>(id);
    gram_mma_kernel<<<NPAIRS, 256, SMEM_BYTES>>>();
    finalize_kernel<<<1, 1>>>((float*)d_out, out_size);
}

// round 4
// speedup vs baseline: 5.1964x; 1.2538x over previous
#include <cuda_runtime.h>
#include <cuda_bf16.h>
#include <cstdint>
#include <math.h>

#define N 8192
#define D 512
#define BM 128
#define NT (N / BM)                 // 64
#define NPAIRS (NT * (NT + 1) / 2)  // 2080
#define BK 64                       // K elements per chunk
#define NCHUNKS (D / BK)            // 8
#define NSTAGE 3
#define TILE_BYTES (BM * BK * 2)    // 16384 (bf16)
#define SMEM_BYTES (1024 + 2 * NSTAGE * TILE_BYTES)

__device__ __nv_bfloat16 g_nrm[N * D];
__device__ double g_accum;

// ---------------------------------------------------------------------------
// PTX helpers (arch-agnostic, sm_80-era)
// ---------------------------------------------------------------------------
__device__ __forceinline__ uint32_t smem_u32(const void* p) {
    uint32_t a;
    asm("{ .reg .u64 t; cvta.to.shared.u64 t, %1; cvt.u32.u64 %0, t; }" : "=r"(a) : "l"(p));
    return a;
}

__device__ __forceinline__ void cp16(uint32_t saddr, const void* g) {
    asm volatile("cp.async.cg.shared.global [%0], [%1], 16;" :: "r"(saddr), "l"(g) : "memory");
}
__device__ __forceinline__ void cp_commit() {
    asm volatile("cp.async.commit_group;" ::: "memory");
}
template <int NN>
__device__ __forceinline__ void cp_wait() {
    asm volatile("cp.async.wait_group %0;" :: "n"(NN) : "memory");
}

__device__ __forceinline__ void ldsm_x4(uint32_t* r, uint32_t addr) {
    asm volatile("ldmatrix.sync.aligned.m8n8.x4.shared.b16 {%0,%1,%2,%3}, [%4];"
                 : "=r"(r[0]), "=r"(r[1]), "=r"(r[2]), "=r"(r[3]) : "r"(addr));
}

__device__ __forceinline__ void mma16816(float* d, const uint32_t* a, uint32_t b0, uint32_t b1) {
    asm volatile(
        "mma.sync.aligned.m16n8k16.row.col.f32.bf16.bf16.f32 "
        "{%0,%1,%2,%3}, {%4,%5,%6,%7}, {%8,%9}, {%0,%1,%2,%3};"
        : "+f"(d[0]), "+f"(d[1]), "+f"(d[2]), "+f"(d[3])
        : "r"(a[0]), "r"(a[1]), "r"(a[2]), "r"(a[3]), "r"(b0), "r"(b1));
}

// ---------------------------------------------------------------------------
// Kernel 1: row L2-normalize fp32 -> bf16. One WARP per row, shuffle-only.
// 256 threads / block = 8 rows; grid = 1024.
// ---------------------------------------------------------------------------
__global__ __launch_bounds__(256) void normalize_kernel(const float* __restrict__ in) {
    int row  = blockIdx.x * 8 + (threadIdx.x >> 5);
    int lane = threadIdx.x & 31;
    if (blockIdx.x == 0 && threadIdx.x == 0) g_accum = 0.0;

    const float4* src = (const float4*)(in + (size_t)row * D);
    float4 v[4];
    float ss = 0.0f;
    #pragma unroll
    for (int i = 0; i < 4; i++) {
        v[i] = src[i * 32 + lane];
        ss += v[i].x * v[i].x + v[i].y * v[i].y + v[i].z * v[i].z + v[i].w * v[i].w;
    }
    #pragma unroll
    for (int o = 16; o; o >>= 1) ss += __shfl_xor_sync(0xffffffffu, ss, o);
    float inv = rsqrtf(ss);

    uint2* dst = (uint2*)(g_nrm + (size_t)row * D);
    #pragma unroll
    for (int i = 0; i < 4; i++) {
        __nv_bfloat162 lo = __floats2bfloat162_rn(v[i].x * inv, v[i].y * inv);
        __nv_bfloat162 hi = __floats2bfloat162_rn(v[i].z * inv, v[i].w * inv);
        uint2 o2;
        o2.x = *(uint32_t*)&lo;
        o2.y = *(uint32_t*)&hi;
        dst[i * 32 + lane] = o2;
    }
}

// ---------------------------------------------------------------------------
// Kernel 2: upper-triangle 128x128 Gram tiles via mma.sync bf16 (HMMA).
// 256 threads = 8 warps (2 x 4), warp tile 64x32.
// 3-stage cp.async pipeline, ONE __syncthreads per K-chunk.
// SMEM tiles [128 rows][64 k] bf16, 128B rows, XOR-swizzled 16B chunks.
// ---------------------------------------------------------------------------
extern __shared__ char dynsmem[];

__global__ __launch_bounds__(256, 2) void gram_mma_kernel() {
    int b = blockIdx.x;
    int bj = (int)((sqrtf(8.0f * (float)b + 1.0f) - 1.0f) * 0.5f);
    while ((bj + 1) * (bj + 2) / 2 <= b) bj++;
    while (bj * (bj + 1) / 2 > b) bj--;
    int bi = b - bj * (bj + 1) / 2;

    const __nv_bfloat16* __restrict__ gA = g_nrm + (size_t)bi * BM * D;
    const __nv_bfloat16* __restrict__ gB = g_nrm + (size_t)bj * BM * D;
    const bool diag = (bi == bj);

    int t      = threadIdx.x;
    int wid    = t >> 5;
    int lane   = t & 31;
    int warp_m = wid & 1;    // 2 warps over M (64 each)
    int warp_n = wid >> 1;   // 4 warps over N (32 each)

    uint32_t smem0 = smem_u32(dynsmem);
    uint32_t base  = (smem0 + 1023) & ~1023u;
    uint32_t sA[NSTAGE], sB[NSTAGE];
    #pragma unroll
    for (int s = 0; s < NSTAGE; s++) {
        sA[s] = base + (2 * s)     * TILE_BYTES;
        sB[s] = base + (2 * s + 1) * TILE_BYTES;
    }

    // --- async tile loader: 128 rows x 64 bf16 (= 8 x 16B chunks/row) ---
    auto load_tile = [&](const __nv_bfloat16* __restrict__ g, uint32_t s, int k0) {
        int row = t >> 1;
        const char* gp = (const char*)(g + (size_t)row * D + k0);
        uint32_t srow = s + (uint32_t)row * 128;
        #pragma unroll
        for (int i = 0; i < 4; i++) {
            int c = (t & 1) * 4 + i;
            cp16(srow + (((uint32_t)c ^ (row & 7)) << 4), gp + c * 16);
        }
    };

    float acc[4][4][4];
    #pragma unroll
    for (int mi = 0; mi < 4; mi++)
        #pragma unroll
        for (int nj = 0; nj < 4; nj++)
            #pragma unroll
            for (int r = 0; r < 4; r++) acc[mi][nj][r] = 0.0f;

    // prologue: stages 0 and 1 in flight
    load_tile(gA, sA[0], 0);
    load_tile(gB, sB[0], 0);
    cp_commit();
    load_tile(gA, sA[1], BK);
    load_tile(gB, sB[1], BK);
    cp_commit();

    int a_row = warp_m * 64 + (lane & 15);                            // + mi*16
    int a_kq  = (lane >> 4) * 8;                                      // element k-offset
    int b_row = warp_n * 32 + (lane & 7) + (((lane >> 3) & 1) << 3);  // + p*16

    for (int c = 0; c < NCHUNKS; c++) {
        if (c < NCHUNKS - 1) cp_wait<1>(); else cp_wait<0>();
        __syncthreads();

        // issue load of chunk c+2 into buffer (c+2)%3: free, since every warp
        // has finished computing chunk c-1 (it passed this barrier).
        if (c + 2 < NCHUNKS) {
            load_tile(gA, sA[(c + 2) % NSTAGE], (c + 2) * BK);
            load_tile(gB, sB[(c + 2) % NSTAGE], (c + 2) * BK);
            cp_commit();
        }

        uint32_t a_base = sA[c % NSTAGE], b_base = sB[c % NSTAGE];
        #pragma unroll
        for (int kk = 0; kk < 4; kk++) {
            uint32_t Af[4][4], Bf[2][4];
            int kchunk = (kk * 16 + a_kq) >> 3;   // 16B-chunk index in row (0..7)
            #pragma unroll
            for (int mi = 0; mi < 4; mi++) {
                int r = a_row + mi * 16;
                ldsm_x4(Af[mi], a_base + (uint32_t)r * 128 +
                                (((uint32_t)kchunk ^ (r & 7)) << 4));
            }
            #pragma unroll
            for (int p = 0; p < 2; p++) {
                int r = b_row + p * 16;
                ldsm_x4(Bf[p], b_base + (uint32_t)r * 128 +
                               (((uint32_t)kchunk ^ (r & 7)) << 4));
            }
            #pragma unroll
            for (int mi = 0; mi < 4; mi++)
                #pragma unroll
                for (int nj = 0; nj < 4; nj++)
                    mma16816(acc[mi][nj], Af[mi],
                             Bf[nj >> 1][nj & 1], Bf[nj >> 1][(nj & 1) + 2]);
        }
    }

    // Epilogue: relu + (strict upper mask on diagonal tiles), per-lane sum.
    float local = 0.0f;
    int lrow0 = warp_m * 64 + (lane >> 2);
    int lcol0 = warp_n * 32 + (lane & 3) * 2;
    #pragma unroll
    for (int mi = 0; mi < 4; mi++) {
        #pragma unroll
        for (int nj = 0; nj < 4; nj++) {
            int rm = lrow0 + mi * 16;
            int cn = lcol0 + nj * 8;
            #pragma unroll
            for (int r = 0; r < 4; r++) {
                int im = rm + (r >> 1) * 8;
                int jn = cn + (r & 1);
                float v = acc[mi][nj][r];
                bool ok = diag ? (im < jn) : true;
                if (ok && v > 0.0f) local += v;
            }
        }
    }

    #pragma unroll
    for (int o = 16; o; o >>= 1) local += __shfl_xor_sync(0xffffffffu, local, o);
    __shared__ float red[8];
    if (lane == 0) red[wid] = local;
    __syncthreads();
    if (t == 0) {
        float s = 0.0f;
        #pragma unroll
        for (int w = 0; w < 8; w++) s += red[w];
        atomicAdd(&g_accum, (double)s);
    }
}

// ---------------------------------------------------------------------------
// Kernel 3: finalize. Off-diagonal symmetric sum doubled, mean over N*N.
// ---------------------------------------------------------------------------
__global__ void finalize_kernel(float* __restrict__ out, int out_size) {
    double v = 2.0 * g_accum / ((double)N * (double)N);
    float f = (float)v;
    out[0] = f;
    if (out_size > 1) out[1] = f;
}

extern "C" void kernel_launch(void* const* d_in, const int* in_sizes, int n_in,
                              void* d_out, int out_size) {
    const float* id = (const float*)d_in[0];
    cudaFuncSetAttribute(gram_mma_kernel, cudaFuncAttributeMaxDynamicSharedMemorySize,
                         SMEM_BYTES);
    normalize_kernel<<<N / 8, 256>>>(id);
    gram_mma_kernel<<<NPAIRS, 256, SMEM_BYTES>>>();
    finalize_kernel<<<1, 1>>>((float*)d_out, out_size);
}

// round 5
// speedup vs baseline: 5.4562x; 1.0500x over previous
#include <cuda_runtime.h>
#include <cuda_fp16.h>
#include <cstdint>
#include <math.h>

#define N 8192
#define D 512
#define BM 128
#define NT (N / BM)                 // 64
#define NPAIRS (NT * (NT + 1) / 2)  // 2080
#define BK 64                       // K elements per chunk
#define NCHUNKS (D / BK)            // 8
#define NSTAGE 3
#define TILE_BYTES (BM * BK * 2)    // 16384 (fp16)
#define SMEM_BYTES (1024 + 2 * NSTAGE * TILE_BYTES)

__device__ __half g_nrm[N * D];
__device__ double g_accum;

// ---------------------------------------------------------------------------
// PTX helpers (arch-agnostic, sm_80-era)
// ---------------------------------------------------------------------------
__device__ __forceinline__ uint32_t smem_u32(const void* p) {
    uint32_t a;
    asm("{ .reg .u64 t; cvta.to.shared.u64 t, %1; cvt.u32.u64 %0, t; }" : "=r"(a) : "l"(p));
    return a;
}

__device__ __forceinline__ void cp16(uint32_t saddr, const void* g) {
    asm volatile("cp.async.cg.shared.global [%0], [%1], 16;" :: "r"(saddr), "l"(g) : "memory");
}
__device__ __forceinline__ void cp_commit() {
    asm volatile("cp.async.commit_group;" ::: "memory");
}
template <int NN>
__device__ __forceinline__ void cp_wait() {
    asm volatile("cp.async.wait_group %0;" :: "n"(NN) : "memory");
}

__device__ __forceinline__ void ldsm_x4(uint32_t* r, uint32_t addr) {
    asm volatile("ldmatrix.sync.aligned.m8n8.x4.shared.b16 {%0,%1,%2,%3}, [%4];"
                 : "=r"(r[0]), "=r"(r[1]), "=r"(r[2]), "=r"(r[3]) : "r"(addr));
}

// fp16 inputs, fp16 accumulate: 2x issue rate vs f32 accumulate.
__device__ __forceinline__ void mma16816_f16(uint32_t* d, const uint32_t* a,
                                             uint32_t b0, uint32_t b1) {
    asm volatile(
        "mma.sync.aligned.m16n8k16.row.col.f16.f16.f16.f16 "
        "{%0,%1}, {%2,%3,%4,%5}, {%6,%7}, {%0,%1};"
        : "+r"(d[0]), "+r"(d[1])
        : "r"(a[0]), "r"(a[1]), "r"(a[2]), "r"(a[3]), "r"(b0), "r"(b1));
}

// ---------------------------------------------------------------------------
// Kernel 1: row L2-normalize fp32 -> fp16. One WARP per row, shuffle-only.
// ---------------------------------------------------------------------------
__global__ __launch_bounds__(256) void normalize_kernel(const float* __restrict__ in) {
    int row  = blockIdx.x * 8 + (threadIdx.x >> 5);
    int lane = threadIdx.x & 31;
    if (blockIdx.x == 0 && threadIdx.x == 0) g_accum = 0.0;

    const float4* src = (const float4*)(in + (size_t)row * D);
    float4 v[4];
    float ss = 0.0f;
    #pragma unroll
    for (int i = 0; i < 4; i++) {
        v[i] = src[i * 32 + lane];
        ss += v[i].x * v[i].x + v[i].y * v[i].y + v[i].z * v[i].z + v[i].w * v[i].w;
    }
    #pragma unroll
    for (int o = 16; o; o >>= 1) ss += __shfl_xor_sync(0xffffffffu, ss, o);
    float inv = rsqrtf(ss);

    uint2* dst = (uint2*)(g_nrm + (size_t)row * D);
    #pragma unroll
    for (int i = 0; i < 4; i++) {
        __half2 lo = __floats2half2_rn(v[i].x * inv, v[i].y * inv);
        __half2 hi = __floats2half2_rn(v[i].z * inv, v[i].w * inv);
        uint2 o2;
        o2.x = *(uint32_t*)&lo;
        o2.y = *(uint32_t*)&hi;
        dst[i * 32 + lane] = o2;
    }
}

// ---------------------------------------------------------------------------
// Kernel 2: upper-triangle 128x128 Gram tiles via mma.sync fp16 (HMMA, f16 acc).
// 256 threads = 8 warps (2 x 4), warp tile 64x32.
// 3-stage cp.async pipeline, ONE __syncthreads per K-chunk.
// SMEM tiles [128 rows][64 k] fp16, 128B rows, XOR-swizzled 16B chunks.
// ---------------------------------------------------------------------------
extern __shared__ char dynsmem[];

__global__ __launch_bounds__(256, 2) void gram_mma_kernel() {
    int b = blockIdx.x;
    int bj = (int)((sqrtf(8.0f * (float)b + 1.0f) - 1.0f) * 0.5f);
    while ((bj + 1) * (bj + 2) / 2 <= b) bj++;
    while (bj * (bj + 1) / 2 > b) bj--;
    int bi = b - bj * (bj + 1) / 2;

    const __half* __restrict__ gA = g_nrm + (size_t)bi * BM * D;
    const __half* __restrict__ gB = g_nrm + (size_t)bj * BM * D;
    const bool diag = (bi == bj);

    int t      = threadIdx.x;
    int wid    = t >> 5;
    int lane   = t & 31;
    int warp_m = wid & 1;    // 2 warps over M (64 each)
    int warp_n = wid >> 1;   // 4 warps over N (32 each)

    uint32_t smem0 = smem_u32(dynsmem);
    uint32_t base  = (smem0 + 1023) & ~1023u;
    uint32_t sA[NSTAGE], sB[NSTAGE];
    #pragma unroll
    for (int s = 0; s < NSTAGE; s++) {
        sA[s] = base + (2 * s)     * TILE_BYTES;
        sB[s] = base + (2 * s + 1) * TILE_BYTES;
    }

    // --- async tile loader: 128 rows x 64 fp16 (= 8 x 16B chunks/row) ---
    auto load_tile = [&](const __half* __restrict__ g, uint32_t s, int k0) {
        int row = t >> 1;
        const char* gp = (const char*)(g + (size_t)row * D + k0);
        uint32_t srow = s + (uint32_t)row * 128;
        #pragma unroll
        for (int i = 0; i < 4; i++) {
            int c = (t & 1) * 4 + i;
            cp16(srow + (((uint32_t)c ^ (row & 7)) << 4), gp + c * 16);
        }
    };

    uint32_t acc[4][4][2];
    #pragma unroll
    for (int mi = 0; mi < 4; mi++)
        #pragma unroll
        for (int nj = 0; nj < 4; nj++) {
            acc[mi][nj][0] = 0u;
            acc[mi][nj][1] = 0u;
        }

    // prologue: stages 0 and 1 in flight
    load_tile(gA, sA[0], 0);
    load_tile(gB, sB[0], 0);
    cp_commit();
    load_tile(gA, sA[1], BK);
    load_tile(gB, sB[1], BK);
    cp_commit();

    int a_row = warp_m * 64 + (lane & 15);                            // + mi*16
    int a_kq  = (lane >> 4) * 8;                                      // element k-offset
    int b_row = warp_n * 32 + (lane & 7) + (((lane >> 3) & 1) << 3);  // + p*16

    for (int c = 0; c < NCHUNKS; c++) {
        if (c < NCHUNKS - 1) cp_wait<1>(); else cp_wait<0>();
        __syncthreads();

        if (c + 2 < NCHUNKS) {
            load_tile(gA, sA[(c + 2) % NSTAGE], (c + 2) * BK);
            load_tile(gB, sB[(c + 2) % NSTAGE], (c + 2) * BK);
            cp_commit();
        }

        uint32_t a_base = sA[c % NSTAGE], b_base = sB[c % NSTAGE];
        #pragma unroll
        for (int kk = 0; kk < 4; kk++) {
            uint32_t Af[4][4], Bf[2][4];
            int kchunk = (kk * 16 + a_kq) >> 3;   // 16B-chunk index in row (0..7)
            #pragma unroll
            for (int mi = 0; mi < 4; mi++) {
                int r = a_row + mi * 16;
                ldsm_x4(Af[mi], a_base + (uint32_t)r * 128 +
                                (((uint32_t)kchunk ^ (r & 7)) << 4));
            }
            #pragma unroll
            for (int p = 0; p < 2; p++) {
                int r = b_row + p * 16;
                ldsm_x4(Bf[p], b_base + (uint32_t)r * 128 +
                               (((uint32_t)kchunk ^ (r & 7)) << 4));
            }
            #pragma unroll
            for (int mi = 0; mi < 4; mi++)
                #pragma unroll
                for (int nj = 0; nj < 4; nj++)
                    mma16816_f16(acc[mi][nj], Af[mi],
                                 Bf[nj >> 1][nj & 1], Bf[nj >> 1][(nj & 1) + 2]);
        }
    }

    // Epilogue: relu + (strict upper mask on diagonal tiles), per-lane sum.
    // f16 acc layout: reg0 = (row, col),(row, col+1) packed; reg1 = row+8 same.
    float local = 0.0f;
    int lrow0 = warp_m * 64 + (lane >> 2);
    int lcol0 = warp_n * 32 + (lane & 3) * 2;
    #pragma unroll
    for (int mi = 0; mi < 4; mi++) {
        #pragma unroll
        for (int nj = 0; nj < 4; nj++) {
            int rm = lrow0 + mi * 16;
            int cn = lcol0 + nj * 8;
            #pragma unroll
            for (int r = 0; r < 2; r++) {
                int im = rm + r * 8;
                float2 f2 = __half22float2(*(__half2*)&acc[mi][nj][r]);
                bool ok0 = diag ? (im < cn) : true;
                bool ok1 = diag ? (im < cn + 1) : true;
                if (ok0 && f2.x > 0.0f) local += f2.x;
                if (ok1 && f2.y > 0.0f) local += f2.y;
            }
        }
    }

    #pragma unroll
    for (int o = 16; o; o >>= 1) local += __shfl_xor_sync(0xffffffffu, local, o);
    __shared__ float red[8];
    if (lane == 0) red[wid] = local;
    __syncthreads();
    if (t == 0) {
        float s = 0.0f;
        #pragma unroll
        for (int w = 0; w < 8; w++) s += red[w];
        atomicAdd(&g_accum, (double)s);
    }
}

// ---------------------------------------------------------------------------
// Kernel 3: finalize. Off-diagonal symmetric sum doubled, mean over N*N.
// ---------------------------------------------------------------------------
__global__ void finalize_kernel(float* __restrict__ out, int out_size) {
    double v = 2.0 * g_accum / ((double)N * (double)N);
    float f = (float)v;
    out[0] = f;
    if (out_size > 1) out[1] = f;
}

extern "C" void kernel_launch(void* const* d_in, const int* in_sizes, int n_in,
                              void* d_out, int out_size) {
    const float* id = (const float*)d_in[0];
    cudaFuncSetAttribute(gram_mma_kernel, cudaFuncAttributeMaxDynamicSharedMemorySize,
                         SMEM_BYTES);
    normalize_kernel<<<N / 8, 256>>>(id);
    gram_mma_kernel<<<NPAIRS, 256, SMEM_BYTES>>>();
    finalize_kernel<<<1, 1>>>((float*)d_out, out_size);
}